// round 14
// baseline (speedup 1.0000x reference)
#include <cuda_runtime.h>
#include <cuda_fp16.h>
#include <math.h>
#include <stdint.h>

// Problem constants
#define Bc 4
#define Sc 4
#define Cc 4
#define Lc 512
#define Ec 64
#define Ac 32
#define Hc 8
#define Kc (Sc*Lc + Cc)   // 2052
#define HAc (Hc*Ac)       // 256
#define SCALEF 0.17677669529663687f  // 1/sqrt(32)
#define CSPL 32           // key splits for constants attention
#define VROWG 2112        // padded key-dim row length of fp16 V (16B aligned)
#define NQ   (Bc*Sc*Hc*Lc)   // 65536 query rows
#define ZSPL 2               // chunk-parity splits for attn_seq

typedef unsigned long long u64;

// ---- helpers -------------------------------------------------------------
__device__ __forceinline__ void cp_async16_sh(unsigned dst, const void* src) {
    asm volatile("cp.async.cg.shared.global [%0],[%1],16;" :: "r"(dst), "l"(src));
}
__device__ __forceinline__ float tfr(float x) {   // tf32-rounded value as float
    uint32_t r; asm("cvt.rna.tf32.f32 %0,%1;" : "=r"(r) : "f"(x));
    return __uint_as_float(r);
}
// m16n8k8 tf32 mma, D==C in-place
__device__ __forceinline__ void mma8(float* d, const uint32_t* a, uint32_t b0, uint32_t b1) {
    asm volatile("mma.sync.aligned.m16n8k8.row.col.f32.tf32.tf32.f32 "
        "{%0,%1,%2,%3},{%4,%5,%6,%7},{%8,%9},{%0,%1,%2,%3};"
        : "+f"(d[0]), "+f"(d[1]), "+f"(d[2]), "+f"(d[3])
        : "r"(a[0]), "r"(a[1]), "r"(a[2]), "r"(a[3]), "r"(b0), "r"(b1));
}
// m16n8k16 f16 mma, fp32 accum, D==C in-place
__device__ __forceinline__ void mma16(float* d, const uint32_t* a, uint32_t b0, uint32_t b1) {
    asm volatile("mma.sync.aligned.m16n8k16.row.col.f32.f16.f16.f32 "
        "{%0,%1,%2,%3},{%4,%5,%6,%7},{%8,%9},{%0,%1,%2,%3};"
        : "+f"(d[0]), "+f"(d[1]), "+f"(d[2]), "+f"(d[3])
        : "r"(a[0]), "r"(a[1]), "r"(a[2]), "r"(a[3]), "r"(b0), "r"(b1));
}

// ---------------- scratch (device globals; no allocations allowed) ----------
__device__ float  g_q_s  [Bc*Sc*Hc*Lc*Ac];     // [B,S,H,L,A] pre-scaled, tf32
__device__ float  g_k_all[Bc*Hc*Kc*Ac];        // [B,H,K,A]   tf32
__device__ float  g_v_all[Bc*Hc*Kc*Ac];        // [B,H,K,A]   tf32 (con path)
__device__ __half g_v_h  [Bc*Hc*Ac*VROWG];     // [B,H,A,Kpad] fp16 transposed
__device__ float  g_qc   [Bc*Cc*Hc*Ac];        // [B,C,H,A] (full fp32)
__device__ float  g_cpart[CSPL][Bc*Cc*Hc][33]; // con partials: 32 acc + lsum
__device__ float  g_part [ZSPL*NQ*Ac];         // seq split partial O
__device__ float  g_plsum[ZSPL*NQ];            // seq split partial lsum
__device__ float  g_out_s[Bc*Sc*Lc*HAc];       // [B,S,L,H*A]

// ---------------- 1) sequence QKV projections (tf32 mma) ---------------------
__global__ void __launch_bounds__(128) proj_seq_kernel(
    const float* __restrict__ xq, const float* __restrict__ xk, const float* __restrict__ xv,
    const float* __restrict__ wq, const float* __restrict__ wk, const float* __restrict__ wv)
{
    const int h = blockIdx.x % Hc;
    const int s = (blockIdx.x / Hc) % Sc;
    const int b = blockIdx.x / (Sc*Hc);
    const int bsh = blockIdx.x;
    const int l0t = blockIdx.y * 128;
    const int which = blockIdx.z;

    const float* x = (which==0) ? xq : (which==1) ? xk : xv;
    const float* w = (which==0) ? wq : (which==1) ? wk : wv;

    __shared__ float Xs[128][68];
    __shared__ float Wt[32][68];

    const int tid = threadIdx.x;
    const int wp_ = tid >> 5, lane = tid & 31;
    const int g = lane >> 2, tg = lane & 3;

    const float* wsrc = w + (s*Hc + h)*Ec*Ac;
    for (int i = tid; i < Ec*Ac; i += 128)
        Wt[i & 31][i >> 5] = tfr(wsrc[i]);
    const float* xp = x + ((u64)(b*Sc + s)*Lc + l0t)*Ec;
    for (int i = tid; i < 128*Ec/4; i += 128) {
        const int row = i >> 4, c4 = i & 15;
        float4 v = ((const float4*)xp)[i];
        v.x = tfr(v.x); v.y = tfr(v.y); v.z = tfr(v.z); v.w = tfr(v.w);
        *(float4*)&Xs[row][c4*4] = v;
    }
    __syncthreads();

    float D[2][4][4];
    #pragma unroll
    for (int mt = 0; mt < 2; mt++)
        #pragma unroll
        for (int nt = 0; nt < 4; nt++)
            D[mt][nt][0] = D[mt][nt][1] = D[mt][nt][2] = D[mt][nt][3] = 0.f;

    const int wrow = wp_*32;
    #pragma unroll
    for (int ks = 0; ks < 8; ks++) {
        uint32_t A[2][4];
        #pragma unroll
        for (int mt = 0; mt < 2; mt++) {
            const int rr0 = wrow + mt*16 + g;
            A[mt][0] = __float_as_uint(Xs[rr0    ][ks*8 + tg]);
            A[mt][1] = __float_as_uint(Xs[rr0 + 8][ks*8 + tg]);
            A[mt][2] = __float_as_uint(Xs[rr0    ][ks*8 + tg + 4]);
            A[mt][3] = __float_as_uint(Xs[rr0 + 8][ks*8 + tg + 4]);
        }
        #pragma unroll
        for (int nt = 0; nt < 4; nt++) {
            const uint32_t b0 = __float_as_uint(Wt[nt*8 + g][ks*8 + tg]);
            const uint32_t b1 = __float_as_uint(Wt[nt*8 + g][ks*8 + tg + 4]);
            mma8(D[0][nt], A[0], b0, b1);
            mma8(D[1][nt], A[1], b0, b1);
        }
    }

    #pragma unroll
    for (int mt = 0; mt < 2; mt++) {
        const int rr0 = wrow + mt*16 + g;
        #pragma unroll
        for (int nt = 0; nt < 4; nt++) {
            const int a0 = nt*8 + 2*tg;
            float d0 = D[mt][nt][0], d1 = D[mt][nt][1];
            float d2 = D[mt][nt][2], d3 = D[mt][nt][3];
            if (which == 0) { d0 *= SCALEF; d1 *= SCALEF; d2 *= SCALEF; d3 *= SCALEF; }
            d0 = tfr(d0); d1 = tfr(d1); d2 = tfr(d2); d3 = tfr(d3);

            if (which == 0) {
                float* op = g_q_s + ((u64)bsh*Lc + l0t)*Ac;
                *(float2*)(op + (u64)(rr0    )*Ac + a0) = make_float2(d0, d1);
                *(float2*)(op + (u64)(rr0 + 8)*Ac + a0) = make_float2(d2, d3);
            } else {
                float* base = (which==1) ? g_k_all : g_v_all;
                float* op = base + ((u64)(b*Hc + h)*Kc + s*Lc + l0t)*Ac;
                *(float2*)(op + (u64)(rr0    )*Ac + a0) = make_float2(d0, d1);
                *(float2*)(op + (u64)(rr0 + 8)*Ac + a0) = make_float2(d2, d3);
                if (which == 2) {
                    __half* vh = g_v_h + (u64)(b*Hc + h)*Ac*VROWG + s*Lc + l0t;
                    vh[(u64)(a0    )*VROWG + rr0    ] = __float2half(d0);
                    vh[(u64)(a0 + 1)*VROWG + rr0    ] = __float2half(d1);
                    vh[(u64)(a0    )*VROWG + rr0 + 8] = __float2half(d2);
                    vh[(u64)(a0 + 1)*VROWG + rr0 + 8] = __float2half(d3);
                }
            }
        }
    }
}

// ---------------- 2) constant QKV projections (tiny, fp32) -------------------
__global__ void proj_con_kernel(
    const float* __restrict__ xq, const float* __restrict__ xk, const float* __restrict__ xv,
    const float* __restrict__ wq, const float* __restrict__ wk, const float* __restrict__ wv)
{
    const int h = blockIdx.x % Hc;
    const int c = (blockIdx.x / Hc) % Cc;
    const int b = blockIdx.x / (Cc*Hc);
    const int which = blockIdx.y;

    const float* x = ((which==0) ? xq : (which==1) ? xk : xv) + (b*Cc + c)*Ec;
    const float* w = ((which==0) ? wq : (which==1) ? wk : wv) + (c*Hc + h)*Ec*Ac;
    const int a = threadIdx.x;

    float acc = 0.f;
    #pragma unroll 8
    for (int e = 0; e < Ec; e++)
        acc += __ldg(&x[e]) * __ldg(&w[e*Ac + a]);

    if (which == 0) g_qc[((b*Cc+c)*Hc + h)*Ac + a] = acc;
    else {
        float* base = (which==1) ? g_k_all : g_v_all;
        base[((b*Hc + h)*Kc + (Sc*Lc + c))*Ac + a] = tfr(acc);
        if (which == 2)
            g_v_h[((u64)(b*Hc + h)*Ac + a)*VROWG + Sc*Lc + c] = __float2half(tfr(acc));
    }
}

// ---------------- 3) sequence attention: tf32 QK + fp16 PV, K-parity split ---
// grid (B*S*H=128, 8, 2), block 128 (4 warps). Split z owns chunks ci ≡ z (mod 2).
// Writes unnormalized (O, lsum) partials; combine folds.
#define KROWF 36
#define KBUF  9216
#define VROWH 72
#define VBUF  4608
#define BUFB  (KBUF + VBUF)
#define SM_PB (2*BUFB)
#define PWROWH 72
#define SMEM_MMA (SM_PB + 4*16*PWROWH*2) // 36864

__device__ __forceinline__ void seq_chunk_params(int ci, int ncb, int& kb0, int& nr, int& p0) {
    if (ci == 4*ncb) { kb0 = 2048; nr = 4; p0 = -1; }
    else { const int sk = ci/ncb, cb = ci%ncb; kb0 = sk*512 + cb*64; nr = 64; p0 = cb*64; }
}

__device__ __forceinline__ void mma_load_kv(char* smem, int buf,
        const float4* kb4, const __half* vh, int kb0, int nr, int tid) {
    float*  Ksm = (float*)(smem + buf*BUFB);
    __half* Vsm = (__half*)(smem + buf*BUFB + KBUF);
    #pragma unroll
    for (int it = 0; it < 4; it++) {
        const int i = tid + it*128;
        const int row = i >> 3, f4 = i & 7;
        float* kd = Ksm + row*KROWF + f4*4;
        if (row < nr)
            cp_async16_sh((unsigned)__cvta_generic_to_shared(kd), kb4 + (u64)(kb0+row)*8 + f4);
        else
            *(float4*)kd = make_float4(0.f,0.f,0.f,0.f);
    }
    #pragma unroll
    for (int it = 0; it < 2; it++) {
        const int i = tid + it*128;
        const int a = i >> 3, f = i & 7;
        __half* vd = Vsm + a*VROWH + f*8;
        cp_async16_sh((unsigned)__cvta_generic_to_shared(vd), vh + (u64)a*VROWG + kb0 + f*8);
    }
}

__global__ void __launch_bounds__(128) attn_seq_mma(const int* __restrict__ maskp)
{
    extern __shared__ char smem[];
    const int tid  = threadIdx.x;
    const int w    = tid >> 5, lane = tid & 31;
    const int g    = lane >> 2, tg = lane & 3;
    const int bsh  = blockIdx.x;
    const int ty   = 7 - blockIdx.y;        // heavy tiles first
    const int h    = bsh & 7;
    const int b    = bsh >> 5;
    const int split= blockIdx.z;
    const int msk  = *maskp;

    const int l0 = ty*64 + w*16;
    const int r0 = l0 + g, r1 = l0 + g + 8;

    uint32_t qf[4][4];
    {
        const float* qp = g_q_s + (u64)bsh*Lc*Ac;
        #pragma unroll
        for (int ks = 0; ks < 4; ks++) {
            qf[ks][0] = __float_as_uint(qp[(u64)r0*Ac + ks*8 + tg]);
            qf[ks][1] = __float_as_uint(qp[(u64)r1*Ac + ks*8 + tg]);
            qf[ks][2] = __float_as_uint(qp[(u64)r0*Ac + ks*8 + tg + 4]);
            qf[ks][3] = __float_as_uint(qp[(u64)r1*Ac + ks*8 + tg + 4]);
        }
    }

    const float4*  kb4 = (const float4*)(g_k_all + (u64)(b*Hc + h)*Kc*Ac);
    const __half*  vh  = g_v_h + (u64)(b*Hc + h)*Ac*VROWG;

    const int ncb = msk ? (ty + 1) : 8;
    const int nch = 4*ncb + 1;

    float O[4][4];
    #pragma unroll
    for (int nt = 0; nt < 4; nt++)
        O[nt][0] = O[nt][1] = O[nt][2] = O[nt][3] = 0.f;
    float ls0 = 0.f, ls1 = 0.f;

    __half* Pw = (__half*)(smem + SM_PB) + w*16*PWROWH;

    // first chunk for this split
    if (split < nch) {
        int kb0, nr, p0;
        seq_chunk_params(split, ncb, kb0, nr, p0);
        mma_load_kv(smem, 0, kb4, vh, kb0, nr, tid);
    }
    asm volatile("cp.async.commit_group;");

    int st = 0;
    for (int ci = split; ci < nch; ci += 2) {
        // prefetch ci+2
        if (ci + 2 < nch) {
            int kb0, nr, p0;
            seq_chunk_params(ci + 2, ncb, kb0, nr, p0);
            mma_load_kv(smem, st ^ 1, kb4, vh, kb0, nr, tid);
            asm volatile("cp.async.commit_group;");
            asm volatile("cp.async.wait_group 1;");
        } else {
            asm volatile("cp.async.commit_group;");
            asm volatile("cp.async.wait_group 0;");
        }
        __syncthreads();

        int kb0, nr, p0;
        seq_chunk_params(ci, ncb, kb0, nr, p0);

        float*  Ksm = (float*)(smem + st*BUFB);
        __half* Vsm = (__half*)(smem + st*BUFB + KBUF);

        // ---- QK^T (tf32): S[16][64] ----
        float S[8][4];
        #pragma unroll
        for (int nt = 0; nt < 8; nt++)
            S[nt][0] = S[nt][1] = S[nt][2] = S[nt][3] = 0.f;
        #pragma unroll
        for (int ks = 0; ks < 4; ks++) {
            #pragma unroll
            for (int nt = 0; nt < 8; nt++) {
                const float* kp = Ksm + (nt*8 + g)*KROWF + ks*8 + tg;
                const uint32_t b0 = __float_as_uint(kp[0]);
                const uint32_t b1 = __float_as_uint(kp[4]);
                mma8(S[nt], qf[ks], b0, b1);
            }
        }

        // ---- exp(s-8) + mask -> P smem (fp16) ----
        #pragma unroll
        for (int nt = 0; nt < 8; nt++) {
            const int k0 = nt*8 + 2*tg;
            bool v0, v1, v2, v3;
            if (p0 < 0)        { v0 = (k0 < 4); v1 = (k0 < 3); v2 = v0; v3 = v1; }
            else if (!msk)     { v0 = v1 = v2 = v3 = true; }
            else {
                const int kr = p0 + k0;
                v0 = kr <= r0; v1 = kr + 1 <= r0;
                v2 = kr <= r1; v3 = kr + 1 <= r1;
            }
            const float p0e = v0 ? __expf(S[nt][0] - 8.f) : 0.f;
            const float p1e = v1 ? __expf(S[nt][1] - 8.f) : 0.f;
            const float p2e = v2 ? __expf(S[nt][2] - 8.f) : 0.f;
            const float p3e = v3 ? __expf(S[nt][3] - 8.f) : 0.f;
            ls0 += p0e + p1e;
            ls1 += p2e + p3e;
            *(__half2*)(Pw + g*PWROWH + k0)     = __floats2half2_rn(p0e, p1e);
            *(__half2*)(Pw + (g+8)*PWROWH + k0) = __floats2half2_rn(p2e, p3e);
        }
        __syncwarp();

        // ---- PV (fp16 m16n8k16) ----
        #pragma unroll
        for (int ks = 0; ks < 4; ks++) {
            uint32_t af[4];
            af[0] = *(const uint32_t*)(Pw + g*PWROWH     + ks*16 + 2*tg);
            af[1] = *(const uint32_t*)(Pw + (g+8)*PWROWH + ks*16 + 2*tg);
            af[2] = *(const uint32_t*)(Pw + g*PWROWH     + ks*16 + 8 + 2*tg);
            af[3] = *(const uint32_t*)(Pw + (g+8)*PWROWH + ks*16 + 8 + 2*tg);
            #pragma unroll
            for (int nt = 0; nt < 4; nt++) {
                const __half* vp = Vsm + (nt*8 + g)*VROWH + ks*16 + 2*tg;
                const uint32_t b0 = *(const uint32_t*)(vp);
                const uint32_t b1 = *(const uint32_t*)(vp + 8);
                mma16(O[nt], af, b0, b1);
            }
        }
        __syncwarp();
        __syncthreads();
        st ^= 1;
    }

    // quad-reduce lsum (rows r0, r1)
    ls0 += __shfl_xor_sync(0xffffffffu, ls0, 1);
    ls0 += __shfl_xor_sync(0xffffffffu, ls0, 2);
    ls1 += __shfl_xor_sync(0xffffffffu, ls1, 1);
    ls1 += __shfl_xor_sync(0xffffffffu, ls1, 2);

    // write unnormalized partials
    float* gp = g_part + (u64)split*NQ*Ac;
    #pragma unroll
    for (int nt = 0; nt < 4; nt++) {
        const int col = nt*8 + 2*tg;
        *(float2*)(gp + ((u64)bsh*Lc + r0)*Ac + col) = make_float2(O[nt][0], O[nt][1]);
        *(float2*)(gp + ((u64)bsh*Lc + r1)*Ac + col) = make_float2(O[nt][2], O[nt][3]);
    }
    if (tg == 0) {
        g_plsum[split*NQ + bsh*Lc + r0] = ls0;
        g_plsum[split*NQ + bsh*Lc + r1] = ls1;
    }
}

// ---------------- combine: fold the two K-parity splits ----------------------
__global__ void combine_kernel()
{
    const int idx4 = blockIdx.x * 256 + threadIdx.x;   // float4 index (NQ*8 total)
    const int row = idx4 >> 3;                          // bsh*512 + l
    const float4 a0 = ((const float4*)g_part)[idx4];
    const float4 a1 = ((const float4*)g_part)[idx4 + NQ*Ac/4];
    const float inv = 1.f / (__ldg(&g_plsum[row]) + __ldg(&g_plsum[row + NQ]));

    const int a4  = (idx4 & 7) * 4;
    const int l   = row & (Lc-1);
    const int bsh = row >> 9;
    const int h   = bsh & 7;
    const int bs  = bsh >> 3;

    float4 o;
    o.x = (a0.x + a1.x)*inv; o.y = (a0.y + a1.y)*inv;
    o.z = (a0.z + a1.z)*inv; o.w = (a0.w + a1.w)*inv;
    *(float4*)(g_out_s + ((u64)(bs*Lc + l))*HAc + h*Ac + a4) = o;
}

// ---------------- 4) constants attention: 32-way key split -------------------
__global__ void __launch_bounds__(64) attn_con_kernel()
{
    const int tid = threadIdx.x;
    const int w = tid >> 5, lane = tid & 31;
    const int bch = blockIdx.x;
    const int h = bch % Hc;
    const int b = bch / (Cc*Hc);
    const int split = blockIdx.y;

    const float qa = g_qc[bch*Ac + lane] * SCALEF;
    const float* kb = g_k_all + (b*Hc + h)*Kc*Ac;
    const float* vb = g_v_all + (b*Hc + h)*Kc*Ac;

    const int kstart = split * 65;
    const int kend   = (kstart + 65 < Kc) ? (kstart + 65) : Kc;

    float lsum = 0.f, acc = 0.f;

    for (int k0 = kstart + w*4; k0 < kend; k0 += 8) {
        float sc[4], vv[4];
        #pragma unroll
        for (int i = 0; i < 4; i++) {
            const int k = k0 + i;
            const bool ok = (k < kend);
            const float kv = ok ? __ldg(&kb[k*Ac + lane]) : 0.f;
            vv[i] = ok ? __ldg(&vb[k*Ac + lane]) : 0.f;
            sc[i] = qa * kv;
        }
        #pragma unroll
        for (int off = 16; off > 0; off >>= 1) {
            #pragma unroll
            for (int i = 0; i < 4; i++)
                sc[i] += __shfl_xor_sync(0xffffffff, sc[i], off);
        }
        #pragma unroll
        for (int i = 0; i < 4; i++) {
            const float p = (k0 + i < kend) ? __expf(sc[i]) : 0.f;
            lsum += p;
            acc += p * vv[i];
        }
    }

    __shared__ float sacc[2][32];
    __shared__ float sls[2];
    sacc[w][lane] = acc;
    if (lane == 0) sls[w] = lsum;
    __syncthreads();
    if (w == 0) {
        g_cpart[split][bch][lane] = sacc[0][lane] + sacc[1][lane];
        if (lane == 0) g_cpart[split][bch][32] = sls[0] + sls[1];
    }
}

// ---------------- 5) sequence head projection (fp32 scalar) ------------------
__global__ void head_seq_kernel(const float* __restrict__ hw, float* __restrict__ out)
{
    const int s = blockIdx.x % Sc;
    const int b = blockIdx.x / Sc;
    const int l0 = blockIdx.y * 64;

    __shared__ float Xc[64][64];
    __shared__ float Wt[64][66];

    const int tid = threadIdx.x;
    const int e = tid % 64;
    const int g = tid / 64;

    float acc[16];
    #pragma unroll
    for (int i = 0; i < 16; i++) acc[i] = 0.f;

    const float* xbase = g_out_s + ((b*Sc + s)*Lc + l0)*HAc;
    const float* wbase = hw + s*HAc*Ec;

    for (int f0 = 0; f0 < HAc; f0 += 64) {
        __syncthreads();
        for (int i = tid; i < 64*64; i += 256) {
            const int f = i >> 6, ee = i & 63;
            Wt[ee][f] = wbase[(f0 + f)*Ec + ee];
        }
        for (int i = tid; i < 64*64/4; i += 256) {
            const int r = i >> 4, c4 = i & 15;
            *((float4*)&Xc[r][c4*4]) = *(const float4*)(xbase + r*HAc + f0 + c4*4);
        }
        __syncthreads();

        #pragma unroll
        for (int f = 0; f < 64; f += 2) {
            const float w0 = Wt[e][f], w1 = Wt[e][f+1];
            #pragma unroll
            for (int i = 0; i < 16; i++) {
                const float2 x2 = *(const float2*)&Xc[g*16+i][f];
                acc[i] += x2.x*w0 + x2.y*w1;
            }
        }
    }

    float* op = out + ((b*Sc + s)*Lc + l0)*Ec;
    #pragma unroll
    for (int i = 0; i < 16; i++) op[(g*16+i)*Ec + e] = acc[i];
}

// ---------------- 6) constants head projection + partial fold ----------------
__global__ void head_con_kernel(const float* __restrict__ hw, float* __restrict__ out)
{
    __shared__ float xs[HAc];
    const int bc = blockIdx.x;
    const int tid = threadIdx.x;

    for (int f = tid; f < HAc; f += 64) {
        const int hh = f >> 5, a = f & 31;
        const int bch = bc*Hc + hh;
        float accs = 0.f, ls = 0.f;
        #pragma unroll
        for (int sp = 0; sp < CSPL; sp++) {
            accs += g_cpart[sp][bch][a];
            ls   += g_cpart[sp][bch][32];
        }
        xs[f] = accs / ls;
    }
    __syncthreads();

    const int e = tid;
    const float* w = hw + (bc % Cc)*HAc*Ec;
    float acc = 0.f;
    #pragma unroll 8
    for (int f = 0; f < HAc; f++)
        acc += xs[f] * __ldg(&w[f*Ec + e]);
    out[bc*Ec + e] = acc;
}

// ---------------- launch -----------------------------------------------------
extern "C" void kernel_launch(void* const* d_in, const int* in_sizes, int n_in,
                              void* d_out, int out_size)
{
    const float* qs  = (const float*)d_in[0];
    const float* ks  = (const float*)d_in[1];
    const float* vs  = (const float*)d_in[2];
    const float* qc  = (const float*)d_in[3];
    const float* kc  = (const float*)d_in[4];
    const float* vc  = (const float*)d_in[5];
    const float* qws = (const float*)d_in[6];
    const float* kws = (const float*)d_in[7];
    const float* vws = (const float*)d_in[8];
    const float* qwc = (const float*)d_in[9];
    const float* kwc = (const float*)d_in[10];
    const float* vwc = (const float*)d_in[11];
    const float* hws = (const float*)d_in[12];
    const float* hwc = (const float*)d_in[13];
    const int*  mask = (const int*)d_in[14];

    float* out = (float*)d_out;
    float* seq_out = out;                     // [B,S,L,E]
    float* con_out = out + Bc*Sc*Lc*Ec;       // [B,C,1,E]

    cudaFuncSetAttribute(attn_seq_mma, cudaFuncAttributeMaxDynamicSharedMemorySize, SMEM_MMA);

    proj_seq_kernel<<<dim3(Bc*Sc*Hc, Lc/128, 3), 128>>>(qs, ks, vs, qws, kws, vws);
    proj_con_kernel<<<dim3(Bc*Cc*Hc, 3), 32>>>(qc, kc, vc, qwc, kwc, vwc);
    attn_con_kernel<<<dim3(Bc*Cc*Hc, CSPL), 64>>>();
    attn_seq_mma<<<dim3(Bc*Sc*Hc, 8, ZSPL), 128, SMEM_MMA>>>(mask);
    combine_kernel<<<NQ*8/256, 256>>>();
    head_con_kernel<<<Bc*Cc, 64>>>(hwc, con_out);
    head_seq_kernel<<<dim3(Bc*Sc, Lc/64), 256>>>(hws, seq_out);
}

// round 15
// speedup vs baseline: 1.0772x; 1.0772x over previous
#include <cuda_runtime.h>
#include <cuda_fp16.h>
#include <math.h>
#include <stdint.h>

// Problem constants
#define Bc 4
#define Sc 4
#define Cc 4
#define Lc 512
#define Ec 64
#define Ac 32
#define Hc 8
#define Kc (Sc*Lc + Cc)   // 2052
#define HAc (Hc*Ac)       // 256
#define SCALEF 0.17677669529663687f  // 1/sqrt(32)
#define CSPL 32           // key splits for constants attention
#define VROWG 2112        // padded key-dim row length of fp16 V (16B aligned)

typedef unsigned long long u64;

// ---- helpers -------------------------------------------------------------
__device__ __forceinline__ void cp_async16_sh(unsigned dst, const void* src) {
    asm volatile("cp.async.cg.shared.global [%0],[%1],16;" :: "r"(dst), "l"(src));
}
__device__ __forceinline__ float tfr(float x) {   // tf32-rounded value as float
    uint32_t r; asm("cvt.rna.tf32.f32 %0,%1;" : "=r"(r) : "f"(x));
    return __uint_as_float(r);
}
// m16n8k8 tf32 mma, D==C in-place
__device__ __forceinline__ void mma8(float* d, const uint32_t* a, uint32_t b0, uint32_t b1) {
    asm volatile("mma.sync.aligned.m16n8k8.row.col.f32.tf32.tf32.f32 "
        "{%0,%1,%2,%3},{%4,%5,%6,%7},{%8,%9},{%0,%1,%2,%3};"
        : "+f"(d[0]), "+f"(d[1]), "+f"(d[2]), "+f"(d[3])
        : "r"(a[0]), "r"(a[1]), "r"(a[2]), "r"(a[3]), "r"(b0), "r"(b1));
}
// m16n8k16 f16 mma, fp32 accum, D==C in-place
__device__ __forceinline__ void mma16(float* d, const uint32_t* a, uint32_t b0, uint32_t b1) {
    asm volatile("mma.sync.aligned.m16n8k16.row.col.f32.f16.f16.f32 "
        "{%0,%1,%2,%3},{%4,%5,%6,%7},{%8,%9},{%0,%1,%2,%3};"
        : "+f"(d[0]), "+f"(d[1]), "+f"(d[2]), "+f"(d[3])
        : "r"(a[0]), "r"(a[1]), "r"(a[2]), "r"(a[3]), "r"(b0), "r"(b1));
}

// ---------------- scratch (device globals; no allocations allowed) ----------
__device__ float  g_q_s  [Bc*Sc*Hc*Lc*Ac];     // [B,S,H,L,A] pre-scaled, tf32
__device__ float  g_k_all[Bc*Hc*Kc*Ac];        // [B,H,K,A]   tf32
__device__ float  g_v_all[Bc*Hc*Kc*Ac];        // [B,H,K,A]   tf32 (con path)
__device__ __half g_v_h  [Bc*Hc*Ac*VROWG];     // [B,H,A,Kpad] fp16 transposed
__device__ float  g_qc   [Bc*Cc*Hc*Ac];        // [B,C,H,A] (full fp32)
__device__ float  g_cpart[CSPL][Bc*Cc*Hc][33]; // con partials: 32 acc + lsum
__device__ float  g_out_s[Bc*Sc*Lc*HAc];       // [B,S,L,H*A]

// ---------------- 1) sequence QKV projections (tf32 mma) ---------------------
// grid (B*S*H=128, 4 l-tiles, 3), block 128 (4 warps). Warp: 32 l x 32 a x 64 e.
__global__ void __launch_bounds__(128) proj_seq_kernel(
    const float* __restrict__ xq, const float* __restrict__ xk, const float* __restrict__ xv,
    const float* __restrict__ wq, const float* __restrict__ wk, const float* __restrict__ wv)
{
    const int h = blockIdx.x % Hc;
    const int s = (blockIdx.x / Hc) % Sc;
    const int b = blockIdx.x / (Sc*Hc);
    const int bsh = blockIdx.x;
    const int l0t = blockIdx.y * 128;
    const int which = blockIdx.z;

    const float* x = (which==0) ? xq : (which==1) ? xk : xv;
    const float* w = (which==0) ? wq : (which==1) ? wk : wv;

    __shared__ float Xs[128][68];   // tf32-rounded, padded
    __shared__ float Wt[32][68];    // transposed W, tf32-rounded

    const int tid = threadIdx.x;
    const int wp_ = tid >> 5, lane = tid & 31;
    const int g = lane >> 2, tg = lane & 3;

    const float* wsrc = w + (s*Hc + h)*Ec*Ac;
    for (int i = tid; i < Ec*Ac; i += 128)
        Wt[i & 31][i >> 5] = tfr(wsrc[i]);
    const float* xp = x + ((u64)(b*Sc + s)*Lc + l0t)*Ec;
    for (int i = tid; i < 128*Ec/4; i += 128) {
        const int row = i >> 4, c4 = i & 15;
        float4 v = ((const float4*)xp)[i];
        v.x = tfr(v.x); v.y = tfr(v.y); v.z = tfr(v.z); v.w = tfr(v.w);
        *(float4*)&Xs[row][c4*4] = v;
    }
    __syncthreads();

    float D[2][4][4];
    #pragma unroll
    for (int mt = 0; mt < 2; mt++)
        #pragma unroll
        for (int nt = 0; nt < 4; nt++)
            D[mt][nt][0] = D[mt][nt][1] = D[mt][nt][2] = D[mt][nt][3] = 0.f;

    const int wrow = wp_*32;
    #pragma unroll
    for (int ks = 0; ks < 8; ks++) {
        uint32_t A[2][4];
        #pragma unroll
        for (int mt = 0; mt < 2; mt++) {
            const int rr0 = wrow + mt*16 + g;
            A[mt][0] = __float_as_uint(Xs[rr0    ][ks*8 + tg]);
            A[mt][1] = __float_as_uint(Xs[rr0 + 8][ks*8 + tg]);
            A[mt][2] = __float_as_uint(Xs[rr0    ][ks*8 + tg + 4]);
            A[mt][3] = __float_as_uint(Xs[rr0 + 8][ks*8 + tg + 4]);
        }
        #pragma unroll
        for (int nt = 0; nt < 4; nt++) {
            const uint32_t b0 = __float_as_uint(Wt[nt*8 + g][ks*8 + tg]);
            const uint32_t b1 = __float_as_uint(Wt[nt*8 + g][ks*8 + tg + 4]);
            mma8(D[0][nt], A[0], b0, b1);
            mma8(D[1][nt], A[1], b0, b1);
        }
    }

    // epilogue: tf32-round outputs; q pre-scaled; v also fp16 transposed copy
    #pragma unroll
    for (int mt = 0; mt < 2; mt++) {
        const int rr0 = wrow + mt*16 + g;
        #pragma unroll
        for (int nt = 0; nt < 4; nt++) {
            const int a0 = nt*8 + 2*tg;
            float d0 = D[mt][nt][0], d1 = D[mt][nt][1];
            float d2 = D[mt][nt][2], d3 = D[mt][nt][3];
            if (which == 0) { d0 *= SCALEF; d1 *= SCALEF; d2 *= SCALEF; d3 *= SCALEF; }
            d0 = tfr(d0); d1 = tfr(d1); d2 = tfr(d2); d3 = tfr(d3);

            if (which == 0) {
                float* op = g_q_s + ((u64)bsh*Lc + l0t)*Ac;
                *(float2*)(op + (u64)(rr0    )*Ac + a0) = make_float2(d0, d1);
                *(float2*)(op + (u64)(rr0 + 8)*Ac + a0) = make_float2(d2, d3);
            } else {
                float* base = (which==1) ? g_k_all : g_v_all;
                float* op = base + ((u64)(b*Hc + h)*Kc + s*Lc + l0t)*Ac;
                *(float2*)(op + (u64)(rr0    )*Ac + a0) = make_float2(d0, d1);
                *(float2*)(op + (u64)(rr0 + 8)*Ac + a0) = make_float2(d2, d3);
                if (which == 2) {
                    __half* vh = g_v_h + (u64)(b*Hc + h)*Ac*VROWG + s*Lc + l0t;
                    vh[(u64)(a0    )*VROWG + rr0    ] = __float2half(d0);
                    vh[(u64)(a0 + 1)*VROWG + rr0    ] = __float2half(d1);
                    vh[(u64)(a0    )*VROWG + rr0 + 8] = __float2half(d2);
                    vh[(u64)(a0 + 1)*VROWG + rr0 + 8] = __float2half(d3);
                }
            }
        }
    }
}

// ---------------- 2) constant QKV projections (tiny, fp32) -------------------
__global__ void proj_con_kernel(
    const float* __restrict__ xq, const float* __restrict__ xk, const float* __restrict__ xv,
    const float* __restrict__ wq, const float* __restrict__ wk, const float* __restrict__ wv)
{
    const int h = blockIdx.x % Hc;
    const int c = (blockIdx.x / Hc) % Cc;
    const int b = blockIdx.x / (Cc*Hc);
    const int which = blockIdx.y;

    const float* x = ((which==0) ? xq : (which==1) ? xk : xv) + (b*Cc + c)*Ec;
    const float* w = ((which==0) ? wq : (which==1) ? wk : wv) + (c*Hc + h)*Ec*Ac;
    const int a = threadIdx.x;

    float acc = 0.f;
    #pragma unroll 8
    for (int e = 0; e < Ec; e++)
        acc += __ldg(&x[e]) * __ldg(&w[e*Ac + a]);

    if (which == 0) g_qc[((b*Cc+c)*Hc + h)*Ac + a] = acc;   // fp32 (con path)
    else {
        float* base = (which==1) ? g_k_all : g_v_all;
        base[((b*Hc + h)*Kc + (Sc*Lc + c))*Ac + a] = tfr(acc);
        if (which == 2)
            g_v_h[((u64)(b*Hc + h)*Ac + a)*VROWG + Sc*Lc + c] = __float2half(tfr(acc));
    }
}

// ---------------- 3) sequence attention: tf32 QK + fp16 PV flash -------------
// grid (B*S*H=128, 8), block 128 (4 warps). Warp owns 16 queries; 64-key chunks.
#define KROWF 36                         // K row floats
#define KBUF  9216                       // 64*36*4
#define VROWH 72                         // V smem row halves (144B)
#define VBUF  4608                       // 32*72*2
#define BUFB  (KBUF + VBUF)              // 13824 per stage
#define SM_PB (2*BUFB)                   // 27648
#define PWROWH 72
#define SMEM_MMA (SM_PB + 4*16*PWROWH*2) // 36864

__device__ __forceinline__ void mma_load_kv(char* smem, int buf,
        const float4* kb4, const __half* vh, int kb0, int nr, int tid) {
    float*  Ksm = (float*)(smem + buf*BUFB);
    __half* Vsm = (__half*)(smem + buf*BUFB + KBUF);
    #pragma unroll
    for (int it = 0; it < 4; it++) {
        const int i = tid + it*128;        // 0..511
        const int row = i >> 3, f4 = i & 7;
        float* kd = Ksm + row*KROWF + f4*4;
        if (row < nr)
            cp_async16_sh((unsigned)__cvta_generic_to_shared(kd), kb4 + (u64)(kb0+row)*8 + f4);
        else
            *(float4*)kd = make_float4(0.f,0.f,0.f,0.f);
    }
    #pragma unroll
    for (int it = 0; it < 2; it++) {
        const int i = tid + it*128;        // 0..255
        const int a = i >> 3, f = i & 7;
        __half* vd = Vsm + a*VROWH + f*8;
        cp_async16_sh((unsigned)__cvta_generic_to_shared(vd), vh + (u64)a*VROWG + kb0 + f*8);
    }
}

__global__ void __launch_bounds__(128, 6) attn_seq_mma(const int* __restrict__ maskp)
{
    extern __shared__ char smem[];
    const int tid  = threadIdx.x;
    const int w    = tid >> 5, lane = tid & 31;
    const int g    = lane >> 2, tg = lane & 3;
    const int bsh  = blockIdx.x;
    const int ty   = 7 - blockIdx.y;        // heavy tiles first
    const int h    = bsh & 7;
    const int b    = bsh >> 5;
    const int msk  = *maskp;

    const int l0 = ty*64 + w*16;
    const int r0 = l0 + g, r1 = l0 + g + 8;   // two query rows

    // Q fragments: pre-scaled, pre-rounded tf32 -> plain bit-cast loads
    uint32_t qf[4][4];
    {
        const float* qp = g_q_s + (u64)bsh*Lc*Ac;
        #pragma unroll
        for (int ks = 0; ks < 4; ks++) {
            qf[ks][0] = __float_as_uint(qp[(u64)r0*Ac + ks*8 + tg]);
            qf[ks][1] = __float_as_uint(qp[(u64)r1*Ac + ks*8 + tg]);
            qf[ks][2] = __float_as_uint(qp[(u64)r0*Ac + ks*8 + tg + 4]);
            qf[ks][3] = __float_as_uint(qp[(u64)r1*Ac + ks*8 + tg + 4]);
        }
    }

    const float4*  kb4 = (const float4*)(g_k_all + (u64)(b*Hc + h)*Kc*Ac);
    const __half*  vh  = g_v_h + (u64)(b*Hc + h)*Ac*VROWG;

    const int ncb = msk ? (ty + 1) : 8;      // 64-key chunks per s-block
    const int nch = 4*ncb + 1;               // + const chunk

    float O[4][4];
    #pragma unroll
    for (int nt = 0; nt < 4; nt++)
        O[nt][0] = O[nt][1] = O[nt][2] = O[nt][3] = 0.f;
    float ls0 = 0.f, ls1 = 0.f;

    __half* Pw = (__half*)(smem + SM_PB) + w*16*PWROWH;   // [16][72] this warp

    // chunk 0 load
    mma_load_kv(smem, 0, kb4, vh, 0, 64, tid);
    asm volatile("cp.async.commit_group;");

    for (int ci = 0; ci < nch; ci++) {
        // prefetch ci+1
        if (ci + 1 < nch) {
            int kb0, nr;
            if (ci + 1 == 4*ncb) { kb0 = 2048; nr = 4; }
            else { const int sk = (ci+1)/ncb, cb = (ci+1)%ncb; kb0 = sk*512 + cb*64; nr = 64; }
            mma_load_kv(smem, (ci+1) & 1, kb4, vh, kb0, nr, tid);
            asm volatile("cp.async.commit_group;");
            asm volatile("cp.async.wait_group 1;");
        } else {
            asm volatile("cp.async.commit_group;");
            asm volatile("cp.async.wait_group 0;");
        }
        __syncthreads();

        int p0;   // key offset within L block, or -1 for const chunk
        if (ci == 4*ncb) p0 = -1;
        else p0 = (ci % ncb) * 64;

        float*  Ksm = (float*)(smem + (ci & 1)*BUFB);
        __half* Vsm = (__half*)(smem + (ci & 1)*BUFB + KBUF);

        // ---- QK^T (tf32): S[16][64] ----
        float S[8][4];
        #pragma unroll
        for (int nt = 0; nt < 8; nt++)
            S[nt][0] = S[nt][1] = S[nt][2] = S[nt][3] = 0.f;
        #pragma unroll
        for (int ks = 0; ks < 4; ks++) {
            #pragma unroll
            for (int nt = 0; nt < 8; nt++) {
                const float* kp = Ksm + (nt*8 + g)*KROWF + ks*8 + tg;
                const uint32_t b0 = __float_as_uint(kp[0]);
                const uint32_t b1 = __float_as_uint(kp[4]);
                mma8(S[nt], qf[ks], b0, b1);
            }
        }

        // ---- exp(s-8) + mask -> P smem (fp16) ----
        #pragma unroll
        for (int nt = 0; nt < 8; nt++) {
            const int k0 = nt*8 + 2*tg;
            bool v0, v1, v2, v3;
            if (p0 < 0)        { v0 = (k0 < 4); v1 = (k0 < 3); v2 = v0; v3 = v1; }
            else if (!msk)     { v0 = v1 = v2 = v3 = true; }
            else {
                const int kr = p0 + k0;
                v0 = kr <= r0; v1 = kr + 1 <= r0;
                v2 = kr <= r1; v3 = kr + 1 <= r1;
            }
            const float p0e = v0 ? __expf(S[nt][0] - 8.f) : 0.f;
            const float p1e = v1 ? __expf(S[nt][1] - 8.f) : 0.f;
            const float p2e = v2 ? __expf(S[nt][2] - 8.f) : 0.f;
            const float p3e = v3 ? __expf(S[nt][3] - 8.f) : 0.f;
            ls0 += p0e + p1e;
            ls1 += p2e + p3e;
            *(__half2*)(Pw + g*PWROWH + k0)     = __floats2half2_rn(p0e, p1e);
            *(__half2*)(Pw + (g+8)*PWROWH + k0) = __floats2half2_rn(p2e, p3e);
        }
        __syncwarp();

        // ---- PV (fp16 m16n8k16): O[16][32] += P[16][64] * V[64][32] ----
        #pragma unroll
        for (int ks = 0; ks < 4; ks++) {     // k16 steps over 64 keys
            uint32_t af[4];
            af[0] = *(const uint32_t*)(Pw + g*PWROWH     + ks*16 + 2*tg);
            af[1] = *(const uint32_t*)(Pw + (g+8)*PWROWH + ks*16 + 2*tg);
            af[2] = *(const uint32_t*)(Pw + g*PWROWH     + ks*16 + 8 + 2*tg);
            af[3] = *(const uint32_t*)(Pw + (g+8)*PWROWH + ks*16 + 8 + 2*tg);
            #pragma unroll
            for (int nt = 0; nt < 4; nt++) {
                const __half* vp = Vsm + (nt*8 + g)*VROWH + ks*16 + 2*tg;
                const uint32_t b0 = *(const uint32_t*)(vp);
                const uint32_t b1 = *(const uint32_t*)(vp + 8);
                mma16(O[nt], af, b0, b1);
            }
        }
        __syncwarp();
        __syncthreads();   // all warps done with this buffer before refill
    }

    // lsum across quad (threads sharing the same rows)
    ls0 += __shfl_xor_sync(0xffffffffu, ls0, 1);
    ls0 += __shfl_xor_sync(0xffffffffu, ls0, 2);
    ls1 += __shfl_xor_sync(0xffffffffu, ls1, 1);
    ls1 += __shfl_xor_sync(0xffffffffu, ls1, 2);
    const float i0 = 1.f / ls0, i1 = 1.f / ls1;

    float* ob = g_out_s + (u64)(bsh >> 3)*Lc*HAc + h*Ac;
    #pragma unroll
    for (int nt = 0; nt < 4; nt++) {
        const int col = nt*8 + 2*tg;
        *(float2*)(ob + (u64)r0*HAc + col) = make_float2(O[nt][0]*i0, O[nt][1]*i0);
        *(float2*)(ob + (u64)r1*HAc + col) = make_float2(O[nt][2]*i1, O[nt][3]*i1);
    }
}

// ---------------- 4) constants attention: 32-way key split -------------------
__global__ void __launch_bounds__(64) attn_con_kernel()
{
    const int tid = threadIdx.x;
    const int w = tid >> 5, lane = tid & 31;
    const int bch = blockIdx.x;
    const int h = bch % Hc;
    const int b = bch / (Cc*Hc);
    const int split = blockIdx.y;

    const float qa = g_qc[bch*Ac + lane] * SCALEF;
    const float* kb = g_k_all + (b*Hc + h)*Kc*Ac;
    const float* vb = g_v_all + (b*Hc + h)*Kc*Ac;

    const int kstart = split * 65;
    const int kend   = (kstart + 65 < Kc) ? (kstart + 65) : Kc;

    float lsum = 0.f, acc = 0.f;

    for (int k0 = kstart + w*4; k0 < kend; k0 += 8) {
        float sc[4], vv[4];
        #pragma unroll
        for (int i = 0; i < 4; i++) {
            const int k = k0 + i;
            const bool ok = (k < kend);
            const float kv = ok ? __ldg(&kb[k*Ac + lane]) : 0.f;
            vv[i] = ok ? __ldg(&vb[k*Ac + lane]) : 0.f;
            sc[i] = qa * kv;
        }
        #pragma unroll
        for (int off = 16; off > 0; off >>= 1) {
            #pragma unroll
            for (int i = 0; i < 4; i++)
                sc[i] += __shfl_xor_sync(0xffffffff, sc[i], off);
        }
        #pragma unroll
        for (int i = 0; i < 4; i++) {
            const float p = (k0 + i < kend) ? __expf(sc[i]) : 0.f;
            lsum += p;
            acc += p * vv[i];
        }
    }

    __shared__ float sacc[2][32];
    __shared__ float sls[2];
    sacc[w][lane] = acc;
    if (lane == 0) sls[w] = lsum;
    __syncthreads();
    if (w == 0) {
        g_cpart[split][bch][lane] = sacc[0][lane] + sacc[1][lane];
        if (lane == 0) g_cpart[split][bch][32] = sls[0] + sls[1];
    }
}

// ---------------- 5) sequence head projection (fp32 scalar) ------------------
__global__ void head_seq_kernel(const float* __restrict__ hw, float* __restrict__ out)
{
    const int s = blockIdx.x % Sc;
    const int b = blockIdx.x / Sc;
    const int l0 = blockIdx.y * 64;

    __shared__ float Xc[64][64];
    __shared__ float Wt[64][66];

    const int tid = threadIdx.x;
    const int e = tid % 64;
    const int g = tid / 64;

    float acc[16];
    #pragma unroll
    for (int i = 0; i < 16; i++) acc[i] = 0.f;

    const float* xbase = g_out_s + ((b*Sc + s)*Lc + l0)*HAc;
    const float* wbase = hw + s*HAc*Ec;

    for (int f0 = 0; f0 < HAc; f0 += 64) {
        __syncthreads();
        for (int i = tid; i < 64*64; i += 256) {
            const int f = i >> 6, ee = i & 63;
            Wt[ee][f] = wbase[(f0 + f)*Ec + ee];
        }
        for (int i = tid; i < 64*64/4; i += 256) {
            const int r = i >> 4, c4 = i & 15;
            *((float4*)&Xc[r][c4*4]) = *(const float4*)(xbase + r*HAc + f0 + c4*4);
        }
        __syncthreads();

        #pragma unroll
        for (int f = 0; f < 64; f += 2) {
            const float w0 = Wt[e][f], w1 = Wt[e][f+1];
            #pragma unroll
            for (int i = 0; i < 16; i++) {
                const float2 x2 = *(const float2*)&Xc[g*16+i][f];
                acc[i] += x2.x*w0 + x2.y*w1;
            }
        }
    }

    float* op = out + ((b*Sc + s)*Lc + l0)*Ec;
    #pragma unroll
    for (int i = 0; i < 16; i++) op[(g*16+i)*Ec + e] = acc[i];
}

// ---------------- 6) constants head projection + partial fold ----------------
__global__ void head_con_kernel(const float* __restrict__ hw, float* __restrict__ out)
{
    __shared__ float xs[HAc];
    const int bc = blockIdx.x;
    const int tid = threadIdx.x;

    for (int f = tid; f < HAc; f += 64) {
        const int hh = f >> 5, a = f & 31;
        const int bch = bc*Hc + hh;
        float accs = 0.f, ls = 0.f;
        #pragma unroll
        for (int sp = 0; sp < CSPL; sp++) {
            accs += g_cpart[sp][bch][a];
            ls   += g_cpart[sp][bch][32];
        }
        xs[f] = accs / ls;
    }
    __syncthreads();

    const int e = tid;
    const float* w = hw + (bc % Cc)*HAc*Ec;
    float acc = 0.f;
    #pragma unroll 8
    for (int f = 0; f < HAc; f++)
        acc += xs[f] * __ldg(&w[f*Ec + e]);
    out[bc*Ec + e] = acc;
}

// ---------------- launch -----------------------------------------------------
extern "C" void kernel_launch(void* const* d_in, const int* in_sizes, int n_in,
                              void* d_out, int out_size)
{
    const float* qs  = (const float*)d_in[0];
    const float* ks  = (const float*)d_in[1];
    const float* vs  = (const float*)d_in[2];
    const float* qc  = (const float*)d_in[3];
    const float* kc  = (const float*)d_in[4];
    const float* vc  = (const float*)d_in[5];
    const float* qws = (const float*)d_in[6];
    const float* kws = (const float*)d_in[7];
    const float* vws = (const float*)d_in[8];
    const float* qwc = (const float*)d_in[9];
    const float* kwc = (const float*)d_in[10];
    const float* vwc = (const float*)d_in[11];
    const float* hws = (const float*)d_in[12];
    const float* hwc = (const float*)d_in[13];
    const int*  mask = (const int*)d_in[14];

    float* out = (float*)d_out;
    float* seq_out = out;                     // [B,S,L,E]
    float* con_out = out + Bc*Sc*Lc*Ec;       // [B,C,1,E]

    cudaFuncSetAttribute(attn_seq_mma, cudaFuncAttributeMaxDynamicSharedMemorySize, SMEM_MMA);

    proj_seq_kernel<<<dim3(Bc*Sc*Hc, Lc/128, 3), 128>>>(qs, ks, vs, qws, kws, vws);
    proj_con_kernel<<<dim3(Bc*Cc*Hc, 3), 32>>>(qc, kc, vc, qwc, kwc, vwc);
    attn_con_kernel<<<dim3(Bc*Cc*Hc, CSPL), 64>>>();
    attn_seq_mma<<<dim3(Bc*Sc*Hc, 8), 128, SMEM_MMA>>>(mask);
    head_con_kernel<<<Bc*Cc, 64>>>(hwc, con_out);
    head_seq_kernel<<<dim3(Bc*Sc, Lc/64), 256>>>(hws, seq_out);
}

// round 17
// speedup vs baseline: 1.1311x; 1.0500x over previous
#include <cuda_runtime.h>
#include <cuda_fp16.h>
#include <math.h>
#include <stdint.h>

// Problem constants
#define Bc 4
#define Sc 4
#define Cc 4
#define Lc 512
#define Ec 64
#define Ac 32
#define Hc 8
#define Kc (Sc*Lc + Cc)   // 2052
#define HAc (Hc*Ac)       // 256
#define SCALEF 0.17677669529663687f  // 1/sqrt(32)
#define CSPL 32           // key splits for constants attention
#define VROWG 2112        // padded key-dim row length of fp16 V (16B aligned)

typedef unsigned long long u64;

// ---- helpers -------------------------------------------------------------
__device__ __forceinline__ void cp_async16_sh(unsigned dst, const void* src) {
    asm volatile("cp.async.cg.shared.global [%0],[%1],16;" :: "r"(dst), "l"(src));
}
__device__ __forceinline__ float tfr(float x) {   // tf32-rounded value as float
    uint32_t r; asm("cvt.rna.tf32.f32 %0,%1;" : "=r"(r) : "f"(x));
    return __uint_as_float(r);
}
// pack two floats into fp16x2 (lo in low half == __floats2half2_rn(lo,hi))
__device__ __forceinline__ uint32_t pack_h2(float lo, float hi) {
    uint32_t r; asm("cvt.rn.f16x2.f32 %0,%1,%2;" : "=r"(r) : "f"(hi), "f"(lo));
    return r;
}
// m16n8k8 tf32 mma, D==C in-place
__device__ __forceinline__ void mma8(float* d, const uint32_t* a, uint32_t b0, uint32_t b1) {
    asm volatile("mma.sync.aligned.m16n8k8.row.col.f32.tf32.tf32.f32 "
        "{%0,%1,%2,%3},{%4,%5,%6,%7},{%8,%9},{%0,%1,%2,%3};"
        : "+f"(d[0]), "+f"(d[1]), "+f"(d[2]), "+f"(d[3])
        : "r"(a[0]), "r"(a[1]), "r"(a[2]), "r"(a[3]), "r"(b0), "r"(b1));
}
// m16n8k16 f16 mma, fp32 accum, D==C in-place
__device__ __forceinline__ void mma16(float* d, const uint32_t* a, uint32_t b0, uint32_t b1) {
    asm volatile("mma.sync.aligned.m16n8k16.row.col.f32.f16.f16.f32 "
        "{%0,%1,%2,%3},{%4,%5,%6,%7},{%8,%9},{%0,%1,%2,%3};"
        : "+f"(d[0]), "+f"(d[1]), "+f"(d[2]), "+f"(d[3])
        : "r"(a[0]), "r"(a[1]), "r"(a[2]), "r"(a[3]), "r"(b0), "r"(b1));
}

// ---------------- scratch (device globals; no allocations allowed) ----------
__device__ float  g_q_s  [Bc*Sc*Hc*Lc*Ac];     // [B,S,H,L,A] pre-scaled, tf32
__device__ float  g_k_all[Bc*Hc*Kc*Ac];        // [B,H,K,A]   tf32
__device__ float  g_v_all[Bc*Hc*Kc*Ac];        // [B,H,K,A]   tf32 (con path)
__device__ __half g_v_h  [Bc*Hc*Ac*VROWG];     // [B,H,A,Kpad] fp16 transposed
__device__ float  g_qc   [Bc*Cc*Hc*Ac];        // [B,C,H,A] (full fp32)
__device__ float  g_cpart[CSPL][Bc*Cc*Hc][33]; // con partials: 32 acc + lsum
__device__ float  g_out_s[Bc*Sc*Lc*HAc];       // [B,S,L,H*A]

// ---------------- 1) sequence QKV projections (tf32 mma) ---------------------
// grid (B*S*H=128, 4 l-tiles, 3), block 128 (4 warps). Warp: 32 l x 32 a x 64 e.
__global__ void __launch_bounds__(128) proj_seq_kernel(
    const float* __restrict__ xq, const float* __restrict__ xk, const float* __restrict__ xv,
    const float* __restrict__ wq, const float* __restrict__ wk, const float* __restrict__ wv)
{
    const int h = blockIdx.x % Hc;
    const int s = (blockIdx.x / Hc) % Sc;
    const int b = blockIdx.x / (Sc*Hc);
    const int bsh = blockIdx.x;
    const int l0t = blockIdx.y * 128;
    const int which = blockIdx.z;

    const float* x = (which==0) ? xq : (which==1) ? xk : xv;
    const float* w = (which==0) ? wq : (which==1) ? wk : wv;

    __shared__ float Xs[128][68];   // tf32-rounded, padded
    __shared__ float Wt[32][68];    // transposed W, tf32-rounded

    const int tid = threadIdx.x;
    const int wp_ = tid >> 5, lane = tid & 31;
    const int g = lane >> 2, tg = lane & 3;

    const float* wsrc = w + (s*Hc + h)*Ec*Ac;
    for (int i = tid; i < Ec*Ac; i += 128)
        Wt[i & 31][i >> 5] = tfr(wsrc[i]);
    const float* xp = x + ((u64)(b*Sc + s)*Lc + l0t)*Ec;
    for (int i = tid; i < 128*Ec/4; i += 128) {
        const int row = i >> 4, c4 = i & 15;
        float4 v = ((const float4*)xp)[i];
        v.x = tfr(v.x); v.y = tfr(v.y); v.z = tfr(v.z); v.w = tfr(v.w);
        *(float4*)&Xs[row][c4*4] = v;
    }
    __syncthreads();

    float D[2][4][4];
    #pragma unroll
    for (int mt = 0; mt < 2; mt++)
        #pragma unroll
        for (int nt = 0; nt < 4; nt++)
            D[mt][nt][0] = D[mt][nt][1] = D[mt][nt][2] = D[mt][nt][3] = 0.f;

    const int wrow = wp_*32;
    #pragma unroll
    for (int ks = 0; ks < 8; ks++) {
        uint32_t A[2][4];
        #pragma unroll
        for (int mt = 0; mt < 2; mt++) {
            const int rr0 = wrow + mt*16 + g;
            A[mt][0] = __float_as_uint(Xs[rr0    ][ks*8 + tg]);
            A[mt][1] = __float_as_uint(Xs[rr0 + 8][ks*8 + tg]);
            A[mt][2] = __float_as_uint(Xs[rr0    ][ks*8 + tg + 4]);
            A[mt][3] = __float_as_uint(Xs[rr0 + 8][ks*8 + tg + 4]);
        }
        #pragma unroll
        for (int nt = 0; nt < 4; nt++) {
            const uint32_t b0 = __float_as_uint(Wt[nt*8 + g][ks*8 + tg]);
            const uint32_t b1 = __float_as_uint(Wt[nt*8 + g][ks*8 + tg + 4]);
            mma8(D[0][nt], A[0], b0, b1);
            mma8(D[1][nt], A[1], b0, b1);
        }
    }

    // epilogue: tf32-round outputs; q pre-scaled; v also fp16 transposed copy
    #pragma unroll
    for (int mt = 0; mt < 2; mt++) {
        const int rr0 = wrow + mt*16 + g;
        #pragma unroll
        for (int nt = 0; nt < 4; nt++) {
            const int a0 = nt*8 + 2*tg;
            float d0 = D[mt][nt][0], d1 = D[mt][nt][1];
            float d2 = D[mt][nt][2], d3 = D[mt][nt][3];
            if (which == 0) { d0 *= SCALEF; d1 *= SCALEF; d2 *= SCALEF; d3 *= SCALEF; }
            d0 = tfr(d0); d1 = tfr(d1); d2 = tfr(d2); d3 = tfr(d3);

            if (which == 0) {
                float* op = g_q_s + ((u64)bsh*Lc + l0t)*Ac;
                *(float2*)(op + (u64)(rr0    )*Ac + a0) = make_float2(d0, d1);
                *(float2*)(op + (u64)(rr0 + 8)*Ac + a0) = make_float2(d2, d3);
            } else {
                float* base = (which==1) ? g_k_all : g_v_all;
                float* op = base + ((u64)(b*Hc + h)*Kc + s*Lc + l0t)*Ac;
                *(float2*)(op + (u64)(rr0    )*Ac + a0) = make_float2(d0, d1);
                *(float2*)(op + (u64)(rr0 + 8)*Ac + a0) = make_float2(d2, d3);
                if (which == 2) {
                    __half* vh = g_v_h + (u64)(b*Hc + h)*Ac*VROWG + s*Lc + l0t;
                    vh[(u64)(a0    )*VROWG + rr0    ] = __float2half(d0);
                    vh[(u64)(a0 + 1)*VROWG + rr0    ] = __float2half(d1);
                    vh[(u64)(a0    )*VROWG + rr0 + 8] = __float2half(d2);
                    vh[(u64)(a0 + 1)*VROWG + rr0 + 8] = __float2half(d3);
                }
            }
        }
    }
}

// ---------------- 2) constant QKV projections (tiny, fp32) -------------------
__global__ void proj_con_kernel(
    const float* __restrict__ xq, const float* __restrict__ xk, const float* __restrict__ xv,
    const float* __restrict__ wq, const float* __restrict__ wk, const float* __restrict__ wv)
{
    const int h = blockIdx.x % Hc;
    const int c = (blockIdx.x / Hc) % Cc;
    const int b = blockIdx.x / (Cc*Hc);
    const int which = blockIdx.y;

    const float* x = ((which==0) ? xq : (which==1) ? xk : xv) + (b*Cc + c)*Ec;
    const float* w = ((which==0) ? wq : (which==1) ? wk : wv) + (c*Hc + h)*Ec*Ac;
    const int a = threadIdx.x;

    float acc = 0.f;
    #pragma unroll 8
    for (int e = 0; e < Ec; e++)
        acc += __ldg(&x[e]) * __ldg(&w[e*Ac + a]);

    if (which == 0) g_qc[((b*Cc+c)*Hc + h)*Ac + a] = acc;   // fp32 (con path)
    else {
        float* base = (which==1) ? g_k_all : g_v_all;
        base[((b*Hc + h)*Kc + (Sc*Lc + c))*Ac + a] = tfr(acc);
        if (which == 2)
            g_v_h[((u64)(b*Hc + h)*Ac + a)*VROWG + Sc*Lc + c] = __float2half(tfr(acc));
    }
}

// ---------------- 3) sequence attention: tf32 QK + fp16 PV flash -------------
// grid (B*S*H=128, 8), block 128 (4 warps). Warp owns 16 queries; 64-key chunks.
// P never touches smem: the QK C-fragment layout IS the PV A-fragment layout
// (rows {g,g+8}, col pairs {16ks+2tg, 16ks+8+2tg} = score tiles nt=2ks,2ks+1).
#define KROWF 36                         // K row floats
#define KBUF  9216                       // 64*36*4
#define VROWH 72                         // V smem row halves (144B)
#define VBUF  4608                       // 32*72*2
#define BUFB  (KBUF + VBUF)              // 13824 per stage
#define SMEM_MMA (2*BUFB)                // 27648 bytes

__device__ __forceinline__ void mma_load_kv(char* smem, int buf,
        const float4* kb4, const __half* vh, int kb0, int nr, int tid) {
    float*  Ksm = (float*)(smem + buf*BUFB);
    __half* Vsm = (__half*)(smem + buf*BUFB + KBUF);
    #pragma unroll
    for (int it = 0; it < 4; it++) {
        const int i = tid + it*128;        // 0..511
        const int row = i >> 3, f4 = i & 7;
        float* kd = Ksm + row*KROWF + f4*4;
        if (row < nr)
            cp_async16_sh((unsigned)__cvta_generic_to_shared(kd), kb4 + (u64)(kb0+row)*8 + f4);
        else
            *(float4*)kd = make_float4(0.f,0.f,0.f,0.f);
    }
    #pragma unroll
    for (int it = 0; it < 2; it++) {
        const int i = tid + it*128;        // 0..255
        const int a = i >> 3, f = i & 7;
        __half* vd = Vsm + a*VROWH + f*8;
        cp_async16_sh((unsigned)__cvta_generic_to_shared(vd), vh + (u64)a*VROWG + kb0 + f*8);
    }
}

__global__ void __launch_bounds__(128) attn_seq_mma(const int* __restrict__ maskp)
{
    extern __shared__ char smem[];
    const int tid  = threadIdx.x;
    const int w    = tid >> 5, lane = tid & 31;
    const int g    = lane >> 2, tg = lane & 3;
    const int bsh  = blockIdx.x;
    const int ty   = 7 - blockIdx.y;        // heavy tiles first
    const int h    = bsh & 7;
    const int b    = bsh >> 5;
    const int msk  = *maskp;

    const int l0 = ty*64 + w*16;
    const int r0 = l0 + g, r1 = l0 + g + 8;   // two query rows

    // Q fragments: pre-scaled, pre-rounded tf32 -> plain bit-cast loads
    uint32_t qf[4][4];
    {
        const float* qp = g_q_s + (u64)bsh*Lc*Ac;
        #pragma unroll
        for (int ks = 0; ks < 4; ks++) {
            qf[ks][0] = __float_as_uint(qp[(u64)r0*Ac + ks*8 + tg]);
            qf[ks][1] = __float_as_uint(qp[(u64)r1*Ac + ks*8 + tg]);
            qf[ks][2] = __float_as_uint(qp[(u64)r0*Ac + ks*8 + tg + 4]);
            qf[ks][3] = __float_as_uint(qp[(u64)r1*Ac + ks*8 + tg + 4]);
        }
    }

    const float4*  kb4 = (const float4*)(g_k_all + (u64)(b*Hc + h)*Kc*Ac);
    const __half*  vh  = g_v_h + (u64)(b*Hc + h)*Ac*VROWG;

    const int ncb = msk ? (ty + 1) : 8;      // 64-key chunks per s-block
    const int nch = 4*ncb + 1;               // + const chunk

    float O[4][4];
    #pragma unroll
    for (int nt = 0; nt < 4; nt++)
        O[nt][0] = O[nt][1] = O[nt][2] = O[nt][3] = 0.f;
    float ls0 = 0.f, ls1 = 0.f;

    // chunk 0 load
    mma_load_kv(smem, 0, kb4, vh, 0, 64, tid);
    asm volatile("cp.async.commit_group;");

    for (int ci = 0; ci < nch; ci++) {
        // prefetch ci+1
        if (ci + 1 < nch) {
            int kb0, nr;
            if (ci + 1 == 4*ncb) { kb0 = 2048; nr = 4; }
            else { const int sk = (ci+1)/ncb, cb = (ci+1)%ncb; kb0 = sk*512 + cb*64; nr = 64; }
            mma_load_kv(smem, (ci+1) & 1, kb4, vh, kb0, nr, tid);
            asm volatile("cp.async.commit_group;");
            asm volatile("cp.async.wait_group 1;");
        } else {
            asm volatile("cp.async.commit_group;");
            asm volatile("cp.async.wait_group 0;");
        }
        __syncthreads();

        int p0;   // key offset within L block, or -1 for const chunk
        if (ci == 4*ncb) p0 = -1;
        else p0 = (ci % ncb) * 64;

        float*  Ksm = (float*)(smem + (ci & 1)*BUFB);
        __half* Vsm = (__half*)(smem + (ci & 1)*BUFB + KBUF);

        // ---- QK^T (tf32): S[16][64] ----
        float S[8][4];
        #pragma unroll
        for (int nt = 0; nt < 8; nt++)
            S[nt][0] = S[nt][1] = S[nt][2] = S[nt][3] = 0.f;
        #pragma unroll
        for (int ks = 0; ks < 4; ks++) {
            #pragma unroll
            for (int nt = 0; nt < 8; nt++) {
                const float* kp = Ksm + (nt*8 + g)*KROWF + ks*8 + tg;
                const uint32_t b0 = __float_as_uint(kp[0]);
                const uint32_t b1 = __float_as_uint(kp[4]);
                mma8(S[nt], qf[ks], b0, b1);
            }
        }

        // ---- exp(s-8) + mask -> fp16 A-fragments in registers ----
        uint32_t ph0[8], ph1[8];   // ph0: row r0 col pair; ph1: row r1 col pair
        #pragma unroll
        for (int nt = 0; nt < 8; nt++) {
            const int k0 = nt*8 + 2*tg;
            bool v0, v1, v2, v3;
            if (p0 < 0)        { v0 = (k0 < 4); v1 = (k0 < 3); v2 = v0; v3 = v1; }
            else if (!msk)     { v0 = v1 = v2 = v3 = true; }
            else {
                const int kr = p0 + k0;
                v0 = kr <= r0; v1 = kr + 1 <= r0;
                v2 = kr <= r1; v3 = kr + 1 <= r1;
            }
            const float p0e = v0 ? __expf(S[nt][0] - 8.f) : 0.f;
            const float p1e = v1 ? __expf(S[nt][1] - 8.f) : 0.f;
            const float p2e = v2 ? __expf(S[nt][2] - 8.f) : 0.f;
            const float p3e = v3 ? __expf(S[nt][3] - 8.f) : 0.f;
            ls0 += p0e + p1e;
            ls1 += p2e + p3e;
            ph0[nt] = pack_h2(p0e, p1e);
            ph1[nt] = pack_h2(p2e, p3e);
        }

        // ---- PV (fp16 m16n8k16): O[16][32] += P[16][64] * V[64][32] ----
        // A-fragment for k-step ks comes straight from score tiles 2ks, 2ks+1.
        #pragma unroll
        for (int ks = 0; ks < 4; ks++) {
            uint32_t af[4];
            af[0] = ph0[2*ks];       // row r0, k 16ks+2tg,+1
            af[1] = ph1[2*ks];       // row r1, k 16ks+2tg,+1
            af[2] = ph0[2*ks + 1];   // row r0, k 16ks+8+2tg,+1
            af[3] = ph1[2*ks + 1];   // row r1, k 16ks+8+2tg,+1
            #pragma unroll
            for (int nt = 0; nt < 4; nt++) {
                const __half* vp = Vsm + (nt*8 + g)*VROWH + ks*16 + 2*tg;
                const uint32_t b0 = *(const uint32_t*)(vp);
                const uint32_t b1 = *(const uint32_t*)(vp + 8);
                mma16(O[nt], af, b0, b1);
            }
        }
        __syncthreads();   // all warps done with this buffer before refill
    }

    // lsum across quad (threads sharing the same rows)
    ls0 += __shfl_xor_sync(0xffffffffu, ls0, 1);
    ls0 += __shfl_xor_sync(0xffffffffu, ls0, 2);
    ls1 += __shfl_xor_sync(0xffffffffu, ls1, 1);
    ls1 += __shfl_xor_sync(0xffffffffu, ls1, 2);
    const float i0 = 1.f / ls0, i1 = 1.f / ls1;

    float* ob = g_out_s + (u64)(bsh >> 3)*Lc*HAc + h*Ac;
    #pragma unroll
    for (int nt = 0; nt < 4; nt++) {
        const int col = nt*8 + 2*tg;
        *(float2*)(ob + (u64)r0*HAc + col) = make_float2(O[nt][0]*i0, O[nt][1]*i0);
        *(float2*)(ob + (u64)r1*HAc + col) = make_float2(O[nt][2]*i1, O[nt][3]*i1);
    }
}

// ---------------- 4) constants attention: 32-way key split -------------------
__global__ void __launch_bounds__(64) attn_con_kernel()
{
    const int tid = threadIdx.x;
    const int w = tid >> 5, lane = tid & 31;
    const int bch = blockIdx.x;
    const int h = bch % Hc;
    const int b = bch / (Cc*Hc);
    const int split = blockIdx.y;

    const float qa = g_qc[bch*Ac + lane] * SCALEF;
    const float* kb = g_k_all + (b*Hc + h)*Kc*Ac;
    const float* vb = g_v_all + (b*Hc + h)*Kc*Ac;

    const int kstart = split * 65;
    const int kend   = (kstart + 65 < Kc) ? (kstart + 65) : Kc;

    float lsum = 0.f, acc = 0.f;

    for (int k0 = kstart + w*4; k0 < kend; k0 += 8) {
        float sc[4], vv[4];
        #pragma unroll
        for (int i = 0; i < 4; i++) {
            const int k = k0 + i;
            const bool ok = (k < kend);
            const float kv = ok ? __ldg(&kb[k*Ac + lane]) : 0.f;
            vv[i] = ok ? __ldg(&vb[k*Ac + lane]) : 0.f;
            sc[i] = qa * kv;
        }
        #pragma unroll
        for (int off = 16; off > 0; off >>= 1) {
            #pragma unroll
            for (int i = 0; i < 4; i++)
                sc[i] += __shfl_xor_sync(0xffffffff, sc[i], off);
        }
        #pragma unroll
        for (int i = 0; i < 4; i++) {
            const float p = (k0 + i < kend) ? __expf(sc[i]) : 0.f;
            lsum += p;
            acc += p * vv[i];
        }
    }

    __shared__ float sacc[2][32];
    __shared__ float sls[2];
    sacc[w][lane] = acc;
    if (lane == 0) sls[w] = lsum;
    __syncthreads();
    if (w == 0) {
        g_cpart[split][bch][lane] = sacc[0][lane] + sacc[1][lane];
        if (lane == 0) g_cpart[split][bch][32] = sls[0] + sls[1];
    }
}

// ---------------- 5) sequence head projection (fp32 scalar) ------------------
__global__ void head_seq_kernel(const float* __restrict__ hw, float* __restrict__ out)
{
    const int s = blockIdx.x % Sc;
    const int b = blockIdx.x / Sc;
    const int l0 = blockIdx.y * 64;

    __shared__ float Xc[64][64];
    __shared__ float Wt[64][66];

    const int tid = threadIdx.x;
    const int e = tid % 64;
    const int g = tid / 64;

    float acc[16];
    #pragma unroll
    for (int i = 0; i < 16; i++) acc[i] = 0.f;

    const float* xbase = g_out_s + ((b*Sc + s)*Lc + l0)*HAc;
    const float* wbase = hw + s*HAc*Ec;

    for (int f0 = 0; f0 < HAc; f0 += 64) {
        __syncthreads();
        for (int i = tid; i < 64*64; i += 256) {
            const int f = i >> 6, ee = i & 63;
            Wt[ee][f] = wbase[(f0 + f)*Ec + ee];
        }
        for (int i = tid; i < 64*64/4; i += 256) {
            const int r = i >> 4, c4 = i & 15;
            *((float4*)&Xc[r][c4*4]) = *(const float4*)(xbase + r*HAc + f0 + c4*4);
        }
        __syncthreads();

        #pragma unroll
        for (int f = 0; f < 64; f += 2) {
            const float w0 = Wt[e][f], w1 = Wt[e][f+1];
            #pragma unroll
            for (int i = 0; i < 16; i++) {
                const float2 x2 = *(const float2*)&Xc[g*16+i][f];
                acc[i] += x2.x*w0 + x2.y*w1;
            }
        }
    }

    float* op = out + ((b*Sc + s)*Lc + l0)*Ec;
    #pragma unroll
    for (int i = 0; i < 16; i++) op[(g*16+i)*Ec + e] = acc[i];
}

// ---------------- 6) constants head projection + partial fold ----------------
__global__ void head_con_kernel(const float* __restrict__ hw, float* __restrict__ out)
{
    __shared__ float xs[HAc];
    const int bc = blockIdx.x;
    const int tid = threadIdx.x;

    for (int f = tid; f < HAc; f += 64) {
        const int hh = f >> 5, a = f & 31;
        const int bch = bc*Hc + hh;
        float accs = 0.f, ls = 0.f;
        #pragma unroll
        for (int sp = 0; sp < CSPL; sp++) {
            accs += g_cpart[sp][bch][a];
            ls   += g_cpart[sp][bch][32];
        }
        xs[f] = accs / ls;
    }
    __syncthreads();

    const int e = tid;
    const float* w = hw + (bc % Cc)*HAc*Ec;
    float acc = 0.f;
    #pragma unroll 8
    for (int f = 0; f < HAc; f++)
        acc += xs[f] * __ldg(&w[f*Ec + e]);
    out[bc*Ec + e] = acc;
}

// ---------------- launch -----------------------------------------------------
extern "C" void kernel_launch(void* const* d_in, const int* in_sizes, int n_in,
                              void* d_out, int out_size)
{
    const float* qs  = (const float*)d_in[0];
    const float* ks  = (const float*)d_in[1];
    const float* vs  = (const float*)d_in[2];
    const float* qc  = (const float*)d_in[3];
    const float* kc  = (const float*)d_in[4];
    const float* vc  = (const float*)d_in[5];
    const float* qws = (const float*)d_in[6];
    const float* kws = (const float*)d_in[7];
    const float* vws = (const float*)d_in[8];
    const float* qwc = (const float*)d_in[9];
    const float* kwc = (const float*)d_in[10];
    const float* vwc = (const float*)d_in[11];
    const float* hws = (const float*)d_in[12];
    const float* hwc = (const float*)d_in[13];
    const int*  mask = (const int*)d_in[14];

    float* out = (float*)d_out;
    float* seq_out = out;                     // [B,S,L,E]
    float* con_out = out + Bc*Sc*Lc*Ec;       // [B,C,1,E]

    cudaFuncSetAttribute(attn_seq_mma, cudaFuncAttributeMaxDynamicSharedMemorySize, SMEM_MMA);

    proj_seq_kernel<<<dim3(Bc*Sc*Hc, Lc/128, 3), 128>>>(qs, ks, vs, qws, kws, vws);
    proj_con_kernel<<<dim3(Bc*Cc*Hc, 3), 32>>>(qc, kc, vc, qwc, kwc, vwc);
    attn_con_kernel<<<dim3(Bc*Cc*Hc, CSPL), 64>>>();
    attn_seq_mma<<<dim3(Bc*Sc*Hc, 8), 128, SMEM_MMA>>>(mask);
    head_con_kernel<<<Bc*Cc, 64>>>(hwc, con_out);
    head_seq_kernel<<<dim3(Bc*Sc, Lc/64), 256>>>(hws, seq_out);
}